// round 14
// baseline (speedup 1.0000x reference)
#include <cuda_runtime.h>
#include <cuda_fp16.h>
#include <math.h>

#define HNUM 512
#define WNUM 512
#define NIMG 12
#define NPIX (NIMG*HNUM*WNUM)
#define WSTRIDE 176
#define DMAX 11

typedef unsigned long long ull;
typedef unsigned int uint;

// ---- constant weights (host-computed) ----
__constant__ ull   c_g2[6*WSTRIDE];    // {g,g} f32x2 (hpass)
__constant__ ull   c_u2[6*WSTRIDE];    // {u,u} f32x2 (hpass)
__constant__ float c_cn[6];            // -c

// ---- scratch ----
__device__ float  d_diff[NPIX];
__device__ uint   d_AB[(size_t)6*NPIX];   // per-sigma half2{A,B} per pixel
__device__ __half d_S[(size_t)6*NPIX];    // per-sigma box*diff along W (fp16)
__device__ uint4  d_afrag[6*2*DMAX*32];   // mma A-fragments [sigma][stream][d][lane]
__device__ double d_accv[64];

__device__ __forceinline__ int refl(int t){
    int r = t < 0 ? -t : t;
    return r >= HNUM ? (2*HNUM - 2 - r) : r;
}
__device__ __forceinline__ ull pk(float x, float y){
    ull r; asm("mov.b64 %0,{%1,%2};" : "=l"(r) : "f"(x), "f"(y)); return r;
}
__device__ __forceinline__ void upk(ull v, float& x, float& y){
    asm("mov.b64 {%0,%1},%2;" : "=f"(x), "=f"(y) : "l"(v));
}
__device__ __forceinline__ void fma2(ull& d, ull a, ull b){
    asm("fma.rn.f32x2 %0,%1,%2,%0;" : "+l"(d) : "l"(a), "l"(b));
}
__device__ __forceinline__ void hadd2(uint& d, uint a){
    asm("add.f16x2 %0,%0,%1;" : "+r"(d) : "r"(a));
}
__device__ __forceinline__ void hsub2(uint& d, uint a){
    asm("sub.f16x2 %0,%0,%1;" : "+r"(d) : "r"(a));
}
__device__ __forceinline__ float2 h2f(uint v){
    __half2 h = *reinterpret_cast<__half2*>(&v);
    return __half22float2(h);
}
__device__ __forceinline__ uint f2h2(float a, float b){
    __half2 h = __floats2half2_rn(a, b);
    return *reinterpret_cast<uint*>(&h);
}
__device__ __forceinline__ void cpa16(void* s, const void* g){
    unsigned sa = (unsigned)__cvta_generic_to_shared(s);
    asm volatile("cp.async.cg.shared.global [%0], [%1], 16;" :: "r"(sa), "l"(g));
}
__device__ __forceinline__ void cpa_wait(){
    asm volatile("cp.async.commit_group;");
    asm volatile("cp.async.wait_group 0;" ::: "memory");
}
__device__ __forceinline__ void mma16816(float* c, uint4 a, uint b0, uint b1){
    asm volatile("mma.sync.aligned.m16n8k16.row.col.f32.f16.f16.f32 "
        "{%0,%1,%2,%3},{%4,%5,%6,%7},{%8,%9},{%0,%1,%2,%3};"
        : "+f"(c[0]), "+f"(c[1]), "+f"(c[2]), "+f"(c[3])
        : "r"(a.x), "r"(a.y), "r"(a.z), "r"(a.w), "r"(b0), "r"(b1));
}

__global__ void zero_acc(){ d_accv[threadIdx.x] = 0.0; }

// ---- fused diff + per-row prefix + fp16 box-along-W for all sigmas ----
__global__ void __launch_bounds__(256) diff_prefix_kernel(
    const float* __restrict__ in, const float* __restrict__ tg)
{
    __shared__ float dr[512];
    __shared__ float q[667];
    __shared__ float wsum[8];

    const int row = blockIdx.x, img = blockIdx.y;
    const size_t base = ((size_t)img*HNUM + row)*WNUM;
    const int tid = threadIdx.x;

    for (int x = tid; x < 512; x += 256){
        float d = in[base+x] - tg[base+x];
        dr[x] = d;
        d_diff[base+x] = d;
    }
    __syncthreads();

    const int i0 = tid*3;
    float v0 = (i0   < 666) ? dr[refl(i0-77)] : 0.f;
    float v1 = (i0+1 < 666) ? dr[refl(i0-76)] : 0.f;
    float v2 = (i0+2 < 666) ? dr[refl(i0-75)] : 0.f;
    float s01 = v0 + v1;
    float tot = s01 + v2;

    float inc = tot;
#pragma unroll
    for (int off = 1; off < 32; off <<= 1){
        float n = __shfl_up_sync(0xffffffffu, inc, off);
        if ((tid & 31) >= off) inc += n;
    }
    if ((tid & 31) == 31) wsum[tid >> 5] = inc;
    __syncthreads();
    if (tid == 0){
        float a = 0.f;
#pragma unroll
        for (int i = 0; i < 8; ++i){ float t = wsum[i]; wsum[i] = a; a += t; }
    }
    __syncthreads();
    float ex = inc - tot + wsum[tid >> 5];
    if (i0   <= 666) q[i0]   = ex;
    if (i0+1 <= 666) q[i0+1] = ex + v0;
    if (i0+2 <= 666) q[i0+2] = ex + s01;
    __syncthreads();

    const int KS[6] = {5, 11, 21, 39, 77, 155};
#pragma unroll
    for (int s = 0; s < 6; ++s){
        int K = KS[s], P = K >> 1;
        for (int x = tid; x < 512; x += 256){
            int lo = x + 77 - P;
            d_S[(size_t)s*NPIX + base + x] = __float2half(q[lo + K] - q[lo]);
        }
    }
}

// ---- hpass: 4 rows x 512 cols per block; thread = 4 cols x 4 rows (fp32) ----
template<int K, int S>
__global__ void __launch_bounds__(128, 8) hpass_k()
{
    constexpr int P   = K/2;
    constexpr int SH  = ((K + 6)/4)*4;
    constexpr int TS  = 508 + SH;
    extern __shared__ char smraw[];
    ulonglong2* tile = (ulonglong2*)smraw;
    const int sbase = S*WSTRIDE;

    const int tx = threadIdx.x;
    const int r0 = blockIdx.x*4;
    const int img = blockIdx.y;
    const size_t base = ((size_t)img*HNUM + r0)*WNUM;
    const float* src = d_diff + base;

    for (int u = tx; u < TS; u += 128){
        int c = refl(u - P);
        float v0 = src[c], v1 = src[c+WNUM], v2 = src[c+2*WNUM], v3 = src[c+3*WNUM];
        tile[u + (u>>3)] = make_ulonglong2(pk(v0,v1), pk(v2,v3));
    }
    __syncthreads();

    ull aG01[4], aG23[4], aU01[4], aU23[4], wgg[4], wuu[4];
#pragma unroll
    for (int r = 0; r < 4; ++r){
        aG01[r]=0; aG23[r]=0; aU01[r]=0; aU23[r]=0; wgg[r]=0; wuu[r]=0;
    }

    const int w0 = tx*4;
    for (int t0 = 0; t0 < SH; t0 += 4){
#pragma unroll
        for (int j = 0; j < 4; ++j){
            int t = t0 + j;
            wgg[j] = c_g2[sbase + t];
            wuu[j] = c_u2[sbase + t];
            int u = w0 + t;
            ulonglong2 v = tile[u + (u>>3)];
#pragma unroll
            for (int r = 0; r < 4; ++r){
                const int sl = (j - r) & 3;
                fma2(aG01[r], wgg[sl], v.x);
                fma2(aG23[r], wgg[sl], v.y);
                fma2(aU01[r], wuu[sl], v.x);
                fma2(aU23[r], wuu[sl], v.y);
            }
        }
    }

    float A0[4],A1[4],A2[4],A3[4],B0[4],B1[4],B2[4],B3[4];
#pragma unroll
    for (int r = 0; r < 4; ++r){
        upk(aG01[r], A0[r], A1[r]); upk(aG23[r], A2[r], A3[r]);
        upk(aU01[r], B0[r], B1[r]); upk(aU23[r], B2[r], B3[r]);
    }
    uint* dst = d_AB + (size_t)S*NPIX + base + w0;
    *(uint4*)(dst)        = make_uint4(f2h2(A0[0],B0[0]), f2h2(A0[1],B0[1]),
                                       f2h2(A0[2],B0[2]), f2h2(A0[3],B0[3]));
    *(uint4*)(dst+WNUM)   = make_uint4(f2h2(A1[0],B1[0]), f2h2(A1[1],B1[1]),
                                       f2h2(A1[2],B1[2]), f2h2(A1[3],B1[3]));
    *(uint4*)(dst+2*WNUM) = make_uint4(f2h2(A2[0],B2[0]), f2h2(A2[1],B2[1]),
                                       f2h2(A2[2],B2[2]), f2h2(A2[3],B2[3]));
    *(uint4*)(dst+3*WNUM) = make_uint4(f2h2(A3[0],B3[0]), f2h2(A3[1],B3[1]),
                                       f2h2(A3[2],B3[2]), f2h2(A3[3],B3[3]));
}

// ---- vpass (tensor cores): 32 cols x 128 out-rows per block, 256 threads ----
// Out[128,32] = sum_d ( Wu_frag[d] * XA[16d..,32] + Wg_frag[d] * XB[16d..,32] )
// XA/XB staged TRANSPOSED in smem (column-major, packed row-pairs as uint).
template<int K, int S>
__global__ void __launch_bounds__(256, 4) vpass_k(float wloss)
{
    constexpr int P   = K/2;
    constexpr int D   = (K + 30)/16;          // ceil((K+15)/16)
    constexpr int TR  = 112 + 16*D;           // input tile rows
    constexpr int TRu = TR/2 + 1;             // uint row-pairs per column (odd)
    constexpr int XTB = 32*TRu*8;             // XtA + XtB bytes
    constexpr int SBB = TR*80 + 128*64;       // S tile + Sbox bytes
    constexpr int MAXB = (XTB > SBB ? XTB : SBB);
    extern __shared__ char smraw[];
    uint*  smA   = (uint*)smraw;              // [32][TRu]
    uint*  smB   = smA + 32*TRu;
    uint*  tileS = (uint*)smraw;              // reuse: [TR][20] half2 col-pairs
    uint*  sboxs = (uint*)smraw + TR*20;      // [128][16] half2 col-pairs
    float* wred  = (float*)(smraw + MAXB);

    const int tid = threadIdx.x;
    const int lane = tid & 31, warp = tid >> 5;   // 8 warps
    const int g = lane >> 2, j = lane & 3;
    const int m0 = warp * 16;
    const int col0 = blockIdx.x*32;
    const int h0   = blockIdx.y*128;
    const int img  = blockIdx.z;
    const size_t ibase = (size_t)img*(HNUM*WNUM);
    const uint*   ABp = d_AB + (size_t)S*NPIX + ibase;
    const __half* Sp  = d_S  + (size_t)S*NPIX + ibase;

    // ---- fill Xt transposed: i = col + 32*rowpair ----
    for (int i = tid; i < 16*TR; i += 256){
        int rp = i >> 5, col = i & 31;
        int r0i = refl(h0 + 2*rp - P), r1i = refl(h0 + 2*rp + 1 - P);
        uint v0 = ABp[(size_t)r0i*WNUM + col0 + col];
        uint v1 = ABp[(size_t)r1i*WNUM + col0 + col];
        smA[col*TRu + rp] = __byte_perm(v0, v1, 0x5410);   // {A(r+1),A(r)}
        smB[col*TRu + rp] = __byte_perm(v0, v1, 0x7632);   // {B(r+1),B(r)}
    }
    __syncthreads();

    // ---- banded GEMM mainloop ----
    float c[4][4];
#pragma unroll
    for (int nt = 0; nt < 4; ++nt)
#pragma unroll
        for (int r = 0; r < 4; ++r) c[nt][r] = 0.f;

    const uint4* afU = d_afrag + (size_t)(S*2 + 0)*DMAX*32;
    const uint4* afG = d_afrag + (size_t)(S*2 + 1)*DMAX*32;

    for (int d = 0; d < D; ++d){
        uint4 au = __ldg(&afU[d*32 + lane]);
        uint4 ag = __ldg(&afG[d*32 + lane]);
        const int kb = (m0 >> 1) + 8*d + j;
#pragma unroll
        for (int nt = 0; nt < 4; ++nt){
            const int coff = (nt*8 + g)*TRu + kb;
            uint b0 = smA[coff], b1 = smA[coff + 4];
            mma16816(c[nt], au, b0, b1);
            uint e0 = smB[coff], e1 = smB[coff + 4];
            mma16816(c[nt], ag, e0, e1);
        }
    }
    __syncthreads();

    // ---- S tile fill (fp16, [TR][20]) ----
    for (int i = tid; i < TR*4; i += 256){
        int r = i >> 2, cq = i & 3;
        int ro = refl(h0 + r - P);
        cpa16(&tileS[r*20 + 4*cq], Sp + (size_t)ro*WNUM + col0 + 8*cq);
    }
    cpa_wait();
    __syncthreads();

    // ---- Sbox: rolling vertical box, stored to smem ----
    {
        const int p = tid & 15, gg = tid >> 4;
        const int rb = gg*8;
        uint p0=0, p1=0, p2=0, p3=0;
        int t = 0;
        for (; t + 3 < K; t += 4){
            hadd2(p0, tileS[(rb+t  )*20 + p]);
            hadd2(p1, tileS[(rb+t+1)*20 + p]);
            hadd2(p2, tileS[(rb+t+2)*20 + p]);
            hadd2(p3, tileS[(rb+t+3)*20 + p]);
        }
        for (; t < K; ++t)
            hadd2(p0, tileS[(rb+t)*20 + p]);
        hadd2(p0, p1); hadd2(p2, p3); hadd2(p0, p2);
        uint bx = p0;
#pragma unroll
        for (int r = 0; r < 8; ++r){
            if (r){
                hadd2(bx, tileS[(rb + r - 1 + K)*20 + p]);
                hsub2(bx, tileS[(rb + r - 1)*20 + p]);
            }
            sboxs[(rb + r)*16 + p] = bx;
        }
    }
    __syncthreads();

    // ---- epilogue: add -c*box, square, reduce ----
    const float cn = c_cn[S];
    float ls = 0.f;
    const int ra = m0 + g;
#pragma unroll
    for (int nt = 0; nt < 4; ++nt){
        const int cpi = nt*4 + j;
        float2 slo = h2f(sboxs[ra*16 + cpi]);
        float2 shi = h2f(sboxs[(ra+8)*16 + cpi]);
        float o0 = fmaf(cn, slo.x, c[nt][0]);
        float o1 = fmaf(cn, slo.y, c[nt][1]);
        float o2 = fmaf(cn, shi.x, c[nt][2]);
        float o3 = fmaf(cn, shi.y, c[nt][3]);
        ls += o0*o0 + o1*o1 + o2*o2 + o3*o3;
    }
#pragma unroll
    for (int off = 16; off; off >>= 1) ls += __shfl_down_sync(0xffffffffu, ls, off);
    if (lane == 0) wred[warp] = ls;
    __syncthreads();
    if (tid == 0){
        float tot = 0.f;
#pragma unroll
        for (int i = 0; i < 8; ++i) tot += wred[i];
        int slot = (blockIdx.x + blockIdx.y*16 + (blockIdx.z + S)*7) & 63;
        atomicAdd(&d_accv[slot], (double)tot * (double)wloss);
    }
}

// ---- finalize ----
__global__ void final_kernel(float* out){
    double t = 0.0;
#pragma unroll
    for (int i = 0; i < 64; ++i) t += d_accv[i];
    out[0] = (float)(t * (1.0 / (double)NPIX));
}

// ---- host-side weight build ----
static ull   h_g2[6*WSTRIDE];
static ull   h_u2[6*WSTRIDE];
static uint  h_afrag[6*2*DMAX*32*4];
static float h_cn[6];
static float h_wg[6][WSTRIDE];
static float h_wu[6][WSTRIDE];

static inline ull hpackh(float x, float y){
    unsigned a, b; __builtin_memcpy(&a, &x, 4); __builtin_memcpy(&b, &y, 4);
    return (ull)a | ((ull)b << 32);
}
static inline unsigned short f2h_host(float f){
    unsigned x; __builtin_memcpy(&x, &f, 4);
    unsigned sign = (x >> 16) & 0x8000u;
    int exp = (int)((x >> 23) & 0xFF) - 127 + 15;
    unsigned man = x & 0x7FFFFFu;
    if (exp <= 0){
        if (exp < -10) return (unsigned short)sign;
        man |= 0x800000u;
        int shift = 14 - exp;
        unsigned h = man >> shift;
        unsigned rem = man & ((1u << shift) - 1);
        unsigned half = 1u << (shift - 1);
        if (rem > half || (rem == half && (h & 1))) h++;
        return (unsigned short)(sign | h);
    }
    if (exp >= 31) return (unsigned short)(sign | 0x7C00u);
    unsigned h = (unsigned)(exp << 10) | (man >> 13);
    unsigned rem = man & 0x1FFFu;
    if (rem > 0x1000u || (rem == 0x1000u && (h & 1))) h++;
    return (unsigned short)(sign | h);
}

static const int KS_H[6] = {5, 11, 21, 39, 77, 155};

static inline unsigned short wtap(int s, int stream, int t){
    if (t < 0 || t >= KS_H[s]) return 0;
    float w = stream ? h_wg[s][t] : h_wu[s][t];
    return f2h_host(w);
}

static void build_weights(){
    const double sig[6] = {0.6, 1.2, 2.4, 4.8, 9.6, 19.2};
    for (int s = 0; s < 6; ++s){
        int K = KS_H[s], half = K/2;
        double ss = sig[s]*sig[s];
        double sn = 0.3989422804014327 / ss;
        double sg = 0.0, su = 0.0;
        for (int jj = 0; jj < WSTRIDE; ++jj){
            float g = 0.f, u = 0.f;
            if (jj < K){
                double t  = (double)(jj - half);
                double t2 = t*t;
                double e  = exp(-t2 / (2.0*ss));
                g = (float)(e * sn);
                u = (float)((t2 - ss) * e * sn);
                sg += (double)g; su += (double)u;
            }
            h_g2[s*WSTRIDE + jj] = hpackh(g, g);
            h_u2[s*WSTRIDE + jj] = hpackh(u, u);
            h_wg[s][jj] = g;
            h_wu[s][jj] = u;
        }
        h_cn[s] = -(float)(2.0 * sg * su / ((double)K * (double)K));

        // mma A-fragments: A[m][k] = w[16d + k - m], canonical m16n8k16 layout
        for (int stream = 0; stream < 2; ++stream){
            for (int d = 0; d < DMAX; ++d){
                for (int lane = 0; lane < 32; ++lane){
                    int g_ = lane >> 2, j_ = lane & 3;
                    int b = 16*d + 2*j_;
                    uint a0 = (uint)wtap(s,stream, b     - g_    ) | ((uint)wtap(s,stream, b + 1 - g_    ) << 16);
                    uint a1 = (uint)wtap(s,stream, b     - g_ - 8) | ((uint)wtap(s,stream, b + 1 - g_ - 8) << 16);
                    uint a2 = (uint)wtap(s,stream, b + 8 - g_    ) | ((uint)wtap(s,stream, b + 9 - g_    ) << 16);
                    uint a3 = (uint)wtap(s,stream, b + 8 - g_ - 8) | ((uint)wtap(s,stream, b + 9 - g_ - 8) << 16);
                    size_t idx = ((((size_t)s*2 + stream)*DMAX + d)*32 + lane)*4;
                    h_afrag[idx+0] = a0; h_afrag[idx+1] = a1;
                    h_afrag[idx+2] = a2; h_afrag[idx+3] = a3;
                }
            }
        }
    }
}

// per-K smem sizes
static inline int hs_bytes(int K){
    int SH = ((K + 6)/4)*4;
    int TS = 508 + SH;
    int TSP = (TS + TS/8 + 3) & ~1;
    return TSP*16;
}
static inline int vs_bytes(int K){
    int D = (K + 30)/16;
    int TR = 112 + 16*D;
    int TRu = TR/2 + 1;
    int XTB = 32*TRu*8;
    int SBB = TR*80 + 128*64;
    int MAXB = XTB > SBB ? XTB : SBB;
    return MAXB + 64;
}

// ---- capture-dependency helpers (CUDA 13 signatures; no allocations) ----
static bool is_capturing(){
    cudaStreamCaptureStatus st = cudaStreamCaptureStatusNone;
    cudaStreamIsCapturing((cudaStream_t)0, &st);
    return st == cudaStreamCaptureStatusActive;
}
static size_t get_deps(cudaGraphNode_t* out, size_t cap){
    cudaStreamCaptureStatus st;
    const cudaGraphNode_t* deps = nullptr;
    size_t n = 0;
    cudaStreamGetCaptureInfo((cudaStream_t)0, &st, nullptr, nullptr,
                             &deps, nullptr, &n);
    size_t m = (n < cap) ? n : cap;
    for (size_t i = 0; i < m; ++i) out[i] = deps[i];
    return m;
}
static void set_deps(cudaGraphNode_t* d, size_t n){
    cudaStreamUpdateCaptureDependencies((cudaStream_t)0, d, nullptr, n,
                                        cudaStreamSetCaptureDependencies);
}

extern "C" void kernel_launch(void* const* d_in, const int* in_sizes, int n_in,
                              void* d_out, int out_size)
{
    const float* input  = (const float*)d_in[0];
    const float* target = (const float*)d_in[1];
    float* out = (float*)d_out;

    build_weights();
    cudaMemcpyToSymbolAsync(c_g2,    h_g2,    sizeof(h_g2),    0, cudaMemcpyHostToDevice, 0);
    cudaMemcpyToSymbolAsync(c_u2,    h_u2,    sizeof(h_u2),    0, cudaMemcpyHostToDevice, 0);
    cudaMemcpyToSymbolAsync(c_cn,    h_cn,    sizeof(h_cn),    0, cudaMemcpyHostToDevice, 0);
    cudaMemcpyToSymbolAsync(d_afrag, h_afrag, sizeof(h_afrag), 0, cudaMemcpyHostToDevice, 0);

    zero_acc<<<1, 64>>>();
    diff_prefix_kernel<<<dim3(512, NIMG), 256>>>(input, target);

    const bool cap = is_capturing();
    cudaGraphNode_t root[4];
    size_t nroot = 0;
    cudaGraphNode_t vjoin[6];
    size_t nj = 0;

    if (cap) nroot = get_deps(root, 4);

    const dim3 hgrid(128, NIMG);
    const dim3 vgrid(16, 4, NIMG);

    hpass_k<155,5><<<hgrid, 128, hs_bytes(155)>>>();
    vpass_k<155,5><<<vgrid, 256, vs_bytes(155)>>>(10.f);
    if (cap){ nj += get_deps(vjoin + nj, 1); set_deps(root, nroot); }

    hpass_k<77,4><<<hgrid, 128, hs_bytes(77)>>>();
    vpass_k<77,4><<<vgrid, 256, vs_bytes(77)>>>(10.f);
    if (cap){ nj += get_deps(vjoin + nj, 1); set_deps(root, nroot); }

    hpass_k<39,3><<<hgrid, 128, hs_bytes(39)>>>();
    vpass_k<39,3><<<vgrid, 256, vs_bytes(39)>>>(20.f);
    if (cap){ nj += get_deps(vjoin + nj, 1); set_deps(root, nroot); }

    hpass_k<21,2><<<hgrid, 128, hs_bytes(21)>>>();
    vpass_k<21,2><<<vgrid, 256, vs_bytes(21)>>>(400.f);
    if (cap){ nj += get_deps(vjoin + nj, 1); set_deps(root, nroot); }

    hpass_k<11,1><<<hgrid, 128, hs_bytes(11)>>>();
    vpass_k<11,1><<<vgrid, 256, vs_bytes(11)>>>(500.f);
    if (cap){ nj += get_deps(vjoin + nj, 1); set_deps(root, nroot); }

    hpass_k<5,0><<<hgrid, 128, hs_bytes(5)>>>();
    vpass_k<5,0><<<vgrid, 256, vs_bytes(5)>>>(600.f);
    if (cap){ nj += get_deps(vjoin + nj, 1); }

    if (cap && nj > 0) set_deps(vjoin, nj);
    final_kernel<<<1, 1>>>(out);
}

// round 15
// speedup vs baseline: 1.0971x; 1.0971x over previous
#include <cuda_runtime.h>
#include <cuda_fp16.h>
#include <math.h>

#define HNUM 512
#define WNUM 512
#define NIMG 12
#define NPIX (NIMG*HNUM*WNUM)
#define WSTRIDE 176
#define DMAX 11

typedef unsigned long long ull;
typedef unsigned int uint;

// ---- constant weights (host-computed) ----
__constant__ ull   c_g2[6*WSTRIDE];    // {g,g} f32x2 (hpass)
__constant__ ull   c_u2[6*WSTRIDE];    // {u,u} f32x2 (hpass)
__constant__ uint  c_ugh[6*WSTRIDE];   // half2{u,g}  (scalar vpass)
__constant__ float c_cn[6];            // -c

// ---- scratch ----
__device__ float  d_diff[NPIX];
__device__ uint   d_AB[(size_t)6*NPIX];   // per-sigma half2{A,B} per pixel
__device__ __half d_S[(size_t)6*NPIX];    // per-sigma box*diff along W (fp16)
__device__ uint4  d_afrag[6*2*DMAX*32];   // mma A-fragments [sigma][stream][d][lane]
__device__ double d_accv[64];

__device__ __forceinline__ int refl(int t){
    int r = t < 0 ? -t : t;
    return r >= HNUM ? (2*HNUM - 2 - r) : r;
}
__device__ __forceinline__ ull pk(float x, float y){
    ull r; asm("mov.b64 %0,{%1,%2};" : "=l"(r) : "f"(x), "f"(y)); return r;
}
__device__ __forceinline__ void upk(ull v, float& x, float& y){
    asm("mov.b64 {%0,%1},%2;" : "=f"(x), "=f"(y) : "l"(v));
}
__device__ __forceinline__ void fma2(ull& d, ull a, ull b){
    asm("fma.rn.f32x2 %0,%1,%2,%0;" : "+l"(d) : "l"(a), "l"(b));
}
__device__ __forceinline__ void hfma2(uint& d, uint a, uint b){
    asm("fma.rn.f16x2 %0,%1,%2,%0;" : "+r"(d) : "r"(a), "r"(b));
}
__device__ __forceinline__ void hadd2(uint& d, uint a){
    asm("add.f16x2 %0,%0,%1;" : "+r"(d) : "r"(a));
}
__device__ __forceinline__ void hsub2(uint& d, uint a){
    asm("sub.f16x2 %0,%0,%1;" : "+r"(d) : "r"(a));
}
__device__ __forceinline__ float2 h2f(uint v){
    __half2 h = *reinterpret_cast<__half2*>(&v);
    return __half22float2(h);
}
__device__ __forceinline__ uint f2h2(float a, float b){
    __half2 h = __floats2half2_rn(a, b);
    return *reinterpret_cast<uint*>(&h);
}
__device__ __forceinline__ void cpa16(void* s, const void* g){
    unsigned sa = (unsigned)__cvta_generic_to_shared(s);
    asm volatile("cp.async.cg.shared.global [%0], [%1], 16;" :: "r"(sa), "l"(g));
}
__device__ __forceinline__ void cpa_wait(){
    asm volatile("cp.async.commit_group;");
    asm volatile("cp.async.wait_group 0;" ::: "memory");
}
__device__ __forceinline__ void mma16816(float* c, uint4 a, uint b0, uint b1){
    asm volatile("mma.sync.aligned.m16n8k16.row.col.f32.f16.f16.f32 "
        "{%0,%1,%2,%3},{%4,%5,%6,%7},{%8,%9},{%0,%1,%2,%3};"
        : "+f"(c[0]), "+f"(c[1]), "+f"(c[2]), "+f"(c[3])
        : "r"(a.x), "r"(a.y), "r"(a.z), "r"(a.w), "r"(b0), "r"(b1));
}

__global__ void zero_acc(){ d_accv[threadIdx.x] = 0.0; }

// ---- fused diff + per-row prefix + fp16 box-along-W for all sigmas ----
__global__ void __launch_bounds__(256) diff_prefix_kernel(
    const float* __restrict__ in, const float* __restrict__ tg)
{
    __shared__ float dr[512];
    __shared__ float q[667];
    __shared__ float wsum[8];

    const int row = blockIdx.x, img = blockIdx.y;
    const size_t base = ((size_t)img*HNUM + row)*WNUM;
    const int tid = threadIdx.x;

    for (int x = tid; x < 512; x += 256){
        float d = in[base+x] - tg[base+x];
        dr[x] = d;
        d_diff[base+x] = d;
    }
    __syncthreads();

    const int i0 = tid*3;
    float v0 = (i0   < 666) ? dr[refl(i0-77)] : 0.f;
    float v1 = (i0+1 < 666) ? dr[refl(i0-76)] : 0.f;
    float v2 = (i0+2 < 666) ? dr[refl(i0-75)] : 0.f;
    float s01 = v0 + v1;
    float tot = s01 + v2;

    float inc = tot;
#pragma unroll
    for (int off = 1; off < 32; off <<= 1){
        float n = __shfl_up_sync(0xffffffffu, inc, off);
        if ((tid & 31) >= off) inc += n;
    }
    if ((tid & 31) == 31) wsum[tid >> 5] = inc;
    __syncthreads();
    if (tid == 0){
        float a = 0.f;
#pragma unroll
        for (int i = 0; i < 8; ++i){ float t = wsum[i]; wsum[i] = a; a += t; }
    }
    __syncthreads();
    float ex = inc - tot + wsum[tid >> 5];
    if (i0   <= 666) q[i0]   = ex;
    if (i0+1 <= 666) q[i0+1] = ex + v0;
    if (i0+2 <= 666) q[i0+2] = ex + s01;
    __syncthreads();

    const int KS[6] = {5, 11, 21, 39, 77, 155};
#pragma unroll
    for (int s = 0; s < 6; ++s){
        int K = KS[s], P = K >> 1;
        for (int x = tid; x < 512; x += 256){
            int lo = x + 77 - P;
            d_S[(size_t)s*NPIX + base + x] = __float2half(q[lo + K] - q[lo]);
        }
    }
}

// ---- hpass: 4 rows x 512 cols per block; thread = 4 cols x 4 rows (fp32) ----
template<int K, int S>
__global__ void __launch_bounds__(128, 8) hpass_k()
{
    constexpr int P   = K/2;
    constexpr int SH  = ((K + 6)/4)*4;
    constexpr int TS  = 508 + SH;
    extern __shared__ char smraw[];
    ulonglong2* tile = (ulonglong2*)smraw;
    const int sbase = S*WSTRIDE;

    const int tx = threadIdx.x;
    const int r0 = blockIdx.x*4;
    const int img = blockIdx.y;
    const size_t base = ((size_t)img*HNUM + r0)*WNUM;
    const float* src = d_diff + base;

    for (int u = tx; u < TS; u += 128){
        int c = refl(u - P);
        float v0 = src[c], v1 = src[c+WNUM], v2 = src[c+2*WNUM], v3 = src[c+3*WNUM];
        tile[u + (u>>3)] = make_ulonglong2(pk(v0,v1), pk(v2,v3));
    }
    __syncthreads();

    ull aG01[4], aG23[4], aU01[4], aU23[4], wgg[4], wuu[4];
#pragma unroll
    for (int r = 0; r < 4; ++r){
        aG01[r]=0; aG23[r]=0; aU01[r]=0; aU23[r]=0; wgg[r]=0; wuu[r]=0;
    }

    const int w0 = tx*4;
    for (int t0 = 0; t0 < SH; t0 += 4){
#pragma unroll
        for (int j = 0; j < 4; ++j){
            int t = t0 + j;
            wgg[j] = c_g2[sbase + t];
            wuu[j] = c_u2[sbase + t];
            int u = w0 + t;
            ulonglong2 v = tile[u + (u>>3)];
#pragma unroll
            for (int r = 0; r < 4; ++r){
                const int sl = (j - r) & 3;
                fma2(aG01[r], wgg[sl], v.x);
                fma2(aG23[r], wgg[sl], v.y);
                fma2(aU01[r], wuu[sl], v.x);
                fma2(aU23[r], wuu[sl], v.y);
            }
        }
    }

    float A0[4],A1[4],A2[4],A3[4],B0[4],B1[4],B2[4],B3[4];
#pragma unroll
    for (int r = 0; r < 4; ++r){
        upk(aG01[r], A0[r], A1[r]); upk(aG23[r], A2[r], A3[r]);
        upk(aU01[r], B0[r], B1[r]); upk(aU23[r], B2[r], B3[r]);
    }
    uint* dst = d_AB + (size_t)S*NPIX + base + w0;
    *(uint4*)(dst)        = make_uint4(f2h2(A0[0],B0[0]), f2h2(A0[1],B0[1]),
                                       f2h2(A0[2],B0[2]), f2h2(A0[3],B0[3]));
    *(uint4*)(dst+WNUM)   = make_uint4(f2h2(A1[0],B1[0]), f2h2(A1[1],B1[1]),
                                       f2h2(A1[2],B1[2]), f2h2(A1[3],B1[3]));
    *(uint4*)(dst+2*WNUM) = make_uint4(f2h2(A2[0],B2[0]), f2h2(A2[1],B2[1]),
                                       f2h2(A2[2],B2[2]), f2h2(A2[3],B2[3]));
    *(uint4*)(dst+3*WNUM) = make_uint4(f2h2(A3[0],B3[0]), f2h2(A3[1],B3[1]),
                                       f2h2(A3[2],B3[2]), f2h2(A3[3],B3[3]));
}

// ---- scalar vpass (small K): 32 cols x 128 rows, 256 threads, HFMA2 ----
template<int K, int S>
__global__ void __launch_bounds__(256, 5) vpass_sc(float wloss)
{
    constexpr int P  = K/2;
    constexpr int SV = ((K + 14)/8)*8;
    constexpr int TR = 120 + SV;
    extern __shared__ char smraw[];
    uint*  tileAB = (uint*)smraw;
    uint*  tileS  = (uint*)smraw;
    float* wred   = (float*)(smraw + (size_t)TR*128);
    const int sbase = S*WSTRIDE;

    const int tid = threadIdx.x;
    const int tx = tid & 15, ty = tid >> 4;
    const int rb = ty*8;
    const int col0 = blockIdx.x*32;
    const int h0   = blockIdx.y*128;
    const int img  = blockIdx.z;
    const size_t ibase = (size_t)img*(HNUM*WNUM);
    const uint*   ABp = d_AB + (size_t)S*NPIX + ibase;
    const __half* Sp  = d_S  + (size_t)S*NPIX + ibase;

    const bool interior = (h0 >= P) && (h0 + TR - P <= HNUM);

    if (interior){
        const uint* g = ABp + (size_t)(h0 - P)*WNUM + col0;
        for (int i = tid; i < TR*8; i += 256){
            int r = i >> 3, c = i & 7;
            int sl = (c + (r >> 3)) & 7;
            cpa16(&tileAB[r*32 + sl*4], g + (size_t)r*WNUM + 4*c);
        }
    } else {
        for (int i = tid; i < TR*8; i += 256){
            int r = i >> 3, c = i & 7;
            int ro = refl(h0 + r - P)*WNUM;
            int sl = (c + (r >> 3)) & 7;
            cpa16(&tileAB[r*32 + sl*4], ABp + ro + col0 + 4*c);
        }
    }
    cpa_wait();
    __syncthreads();

    uint acc0[8], acc1[8], w2[8];
#pragma unroll
    for (int r = 0; r < 8; ++r){ acc0[r]=0; acc1[r]=0; w2[r]=0; }

    for (int t0 = 0; t0 < SV; t0 += 8){
        const int sl = ((tx >> 1) + ((rb + t0) >> 3)) & 7;
        const uint* trow = &tileAB[(rb + t0)*32 + sl*4 + ((2*tx) & 3)];
#pragma unroll
        for (int j = 0; j < 8; ++j){
            w2[j] = c_ugh[sbase + t0 + j];
            uint2 v = *(const uint2*)(trow + j*32);
#pragma unroll
            for (int r = 0; r < 8; ++r){
                const int s = (j - r) & 7;
                hfma2(acc0[r], w2[s], v.x);
                hfma2(acc1[r], w2[s], v.y);
            }
        }
    }
    __syncthreads();

    if (interior){
        const __half* g = Sp + (size_t)(h0 - P)*WNUM + col0;
        for (int i = tid; i < TR*4; i += 256){
            int r = i >> 2, c = i & 3;
            cpa16(&tileS[r*20 + 4*c], g + (size_t)r*WNUM + 8*c);
        }
    } else {
        for (int i = tid; i < TR*4; i += 256){
            int r = i >> 2, c = i & 3;
            int ro = refl(h0 + r - P)*WNUM;
            cpa16(&tileS[r*20 + 4*c], Sp + ro + col0 + 8*c);
        }
    }
    cpa_wait();
    __syncthreads();

    uint p0=0, p1=0, p2=0, p3=0;
    {
        int t = 0;
        for (; t + 3 < K; t += 4){
            hadd2(p0, tileS[(rb+t  )*20 + tx]);
            hadd2(p1, tileS[(rb+t+1)*20 + tx]);
            hadd2(p2, tileS[(rb+t+2)*20 + tx]);
            hadd2(p3, tileS[(rb+t+3)*20 + tx]);
        }
        for (; t < K; ++t)
            hadd2(p0, tileS[(rb+t)*20 + tx]);
    }
    hadd2(p0, p1); hadd2(p2, p3); hadd2(p0, p2);
    uint sbox = p0;

    const float cn = c_cn[S];
    float ls = 0.f;
#pragma unroll
    for (int r = 0; r < 8; ++r){
        if (r){
            hadd2(sbox, tileS[(rb + r - 1 + K)*20 + tx]);
            hsub2(sbox, tileS[(rb + r - 1)*20 + tx]);
        }
        float2 f0 = h2f(acc0[r]);
        float2 f1 = h2f(acc1[r]);
        float2 sb = h2f(sbox);
        float o0 = fmaf(cn, sb.x, f0.x + f0.y);
        float o1 = fmaf(cn, sb.y, f1.x + f1.y);
        ls += o0*o0 + o1*o1;
    }
#pragma unroll
    for (int off = 16; off; off >>= 1) ls += __shfl_down_sync(0xffffffffu, ls, off);
    if ((tid & 31) == 0) wred[tid >> 5] = ls;
    __syncthreads();
    if (tid == 0){
        float tot = 0.f;
#pragma unroll
        for (int i = 0; i < 8; ++i) tot += wred[i];
        int slot = (blockIdx.x + blockIdx.y*16 + (blockIdx.z + S)*7) & 63;
        atomicAdd(&d_accv[slot], (double)tot * (double)wloss);
    }
}

// ---- tensor-core vpass (large K): 32 cols x 128 out-rows, 256 threads ----
template<int K, int S>
__global__ void __launch_bounds__(256, 4) vpass_mma(float wloss)
{
    constexpr int P   = K/2;
    constexpr int D   = (K + 30)/16;
    constexpr int TR  = 112 + 16*D;
    constexpr int TRu = TR/2 + 1;
    constexpr int XTB = 32*TRu*8;
    constexpr int SBB = TR*80 + 128*64;
    constexpr int MAXB = (XTB > SBB ? XTB : SBB);
    extern __shared__ char smraw[];
    uint*  smA   = (uint*)smraw;
    uint*  smB   = smA + 32*TRu;
    uint*  tileS = (uint*)smraw;
    uint*  sboxs = (uint*)smraw + TR*20;
    float* wred  = (float*)(smraw + MAXB);

    const int tid = threadIdx.x;
    const int lane = tid & 31, warp = tid >> 5;
    const int g = lane >> 2, j = lane & 3;
    const int m0 = warp * 16;
    const int col0 = blockIdx.x*32;
    const int h0   = blockIdx.y*128;
    const int img  = blockIdx.z;
    const size_t ibase = (size_t)img*(HNUM*WNUM);
    const uint*   ABp = d_AB + (size_t)S*NPIX + ibase;
    const __half* Sp  = d_S  + (size_t)S*NPIX + ibase;

    for (int i = tid; i < 16*TR; i += 256){
        int rp = i >> 5, col = i & 31;
        int r0i = refl(h0 + 2*rp - P), r1i = refl(h0 + 2*rp + 1 - P);
        uint v0 = ABp[(size_t)r0i*WNUM + col0 + col];
        uint v1 = ABp[(size_t)r1i*WNUM + col0 + col];
        smA[col*TRu + rp] = __byte_perm(v0, v1, 0x5410);
        smB[col*TRu + rp] = __byte_perm(v0, v1, 0x7632);
    }
    __syncthreads();

    float c[4][4];
#pragma unroll
    for (int nt = 0; nt < 4; ++nt)
#pragma unroll
        for (int r = 0; r < 4; ++r) c[nt][r] = 0.f;

    const uint4* afU = d_afrag + (size_t)(S*2 + 0)*DMAX*32;
    const uint4* afG = d_afrag + (size_t)(S*2 + 1)*DMAX*32;

    for (int d = 0; d < D; ++d){
        uint4 au = __ldg(&afU[d*32 + lane]);
        uint4 ag = __ldg(&afG[d*32 + lane]);
        const int kb = (m0 >> 1) + 8*d + j;
#pragma unroll
        for (int nt = 0; nt < 4; ++nt){
            const int coff = (nt*8 + g)*TRu + kb;
            uint b0 = smA[coff], b1 = smA[coff + 4];
            mma16816(c[nt], au, b0, b1);
            uint e0 = smB[coff], e1 = smB[coff + 4];
            mma16816(c[nt], ag, e0, e1);
        }
    }
    __syncthreads();

    for (int i = tid; i < TR*4; i += 256){
        int r = i >> 2, cq = i & 3;
        int ro = refl(h0 + r - P);
        cpa16(&tileS[r*20 + 4*cq], Sp + (size_t)ro*WNUM + col0 + 8*cq);
    }
    cpa_wait();
    __syncthreads();

    {
        const int p = tid & 15, gg = tid >> 4;
        const int rb = gg*8;
        uint p0=0, p1=0, p2=0, p3=0;
        int t = 0;
        for (; t + 3 < K; t += 4){
            hadd2(p0, tileS[(rb+t  )*20 + p]);
            hadd2(p1, tileS[(rb+t+1)*20 + p]);
            hadd2(p2, tileS[(rb+t+2)*20 + p]);
            hadd2(p3, tileS[(rb+t+3)*20 + p]);
        }
        for (; t < K; ++t)
            hadd2(p0, tileS[(rb+t)*20 + p]);
        hadd2(p0, p1); hadd2(p2, p3); hadd2(p0, p2);
        uint bx = p0;
#pragma unroll
        for (int r = 0; r < 8; ++r){
            if (r){
                hadd2(bx, tileS[(rb + r - 1 + K)*20 + p]);
                hsub2(bx, tileS[(rb + r - 1)*20 + p]);
            }
            sboxs[(rb + r)*16 + p] = bx;
        }
    }
    __syncthreads();

    const float cn = c_cn[S];
    float ls = 0.f;
    const int ra = m0 + g;
#pragma unroll
    for (int nt = 0; nt < 4; ++nt){
        const int cpi = nt*4 + j;
        float2 slo = h2f(sboxs[ra*16 + cpi]);
        float2 shi = h2f(sboxs[(ra+8)*16 + cpi]);
        float o0 = fmaf(cn, slo.x, c[nt][0]);
        float o1 = fmaf(cn, slo.y, c[nt][1]);
        float o2 = fmaf(cn, shi.x, c[nt][2]);
        float o3 = fmaf(cn, shi.y, c[nt][3]);
        ls += o0*o0 + o1*o1 + o2*o2 + o3*o3;
    }
#pragma unroll
    for (int off = 16; off; off >>= 1) ls += __shfl_down_sync(0xffffffffu, ls, off);
    if (lane == 0) wred[warp] = ls;
    __syncthreads();
    if (tid == 0){
        float tot = 0.f;
#pragma unroll
        for (int i = 0; i < 8; ++i) tot += wred[i];
        int slot = (blockIdx.x + blockIdx.y*16 + (blockIdx.z + S)*7) & 63;
        atomicAdd(&d_accv[slot], (double)tot * (double)wloss);
    }
}

// ---- finalize ----
__global__ void final_kernel(float* out){
    double t = 0.0;
#pragma unroll
    for (int i = 0; i < 64; ++i) t += d_accv[i];
    out[0] = (float)(t * (1.0 / (double)NPIX));
}

// ---- host-side weight build ----
static ull   h_g2[6*WSTRIDE];
static ull   h_u2[6*WSTRIDE];
static uint  h_ugh[6*WSTRIDE];
static uint  h_afrag[6*2*DMAX*32*4];
static float h_cn[6];
static float h_wg[6][WSTRIDE];
static float h_wu[6][WSTRIDE];

static inline ull hpackh(float x, float y){
    unsigned a, b; __builtin_memcpy(&a, &x, 4); __builtin_memcpy(&b, &y, 4);
    return (ull)a | ((ull)b << 32);
}
static inline unsigned short f2h_host(float f){
    unsigned x; __builtin_memcpy(&x, &f, 4);
    unsigned sign = (x >> 16) & 0x8000u;
    int exp = (int)((x >> 23) & 0xFF) - 127 + 15;
    unsigned man = x & 0x7FFFFFu;
    if (exp <= 0){
        if (exp < -10) return (unsigned short)sign;
        man |= 0x800000u;
        int shift = 14 - exp;
        unsigned h = man >> shift;
        unsigned rem = man & ((1u << shift) - 1);
        unsigned half = 1u << (shift - 1);
        if (rem > half || (rem == half && (h & 1))) h++;
        return (unsigned short)(sign | h);
    }
    if (exp >= 31) return (unsigned short)(sign | 0x7C00u);
    unsigned h = (unsigned)(exp << 10) | (man >> 13);
    unsigned rem = man & 0x1FFFu;
    if (rem > 0x1000u || (rem == 0x1000u && (h & 1))) h++;
    return (unsigned short)(sign | h);
}

static const int KS_H[6] = {5, 11, 21, 39, 77, 155};

static inline unsigned short wtap(int s, int stream, int t){
    if (t < 0 || t >= KS_H[s]) return 0;
    float w = stream ? h_wg[s][t] : h_wu[s][t];
    return f2h_host(w);
}

static void build_weights(){
    const double sig[6] = {0.6, 1.2, 2.4, 4.8, 9.6, 19.2};
    for (int s = 0; s < 6; ++s){
        int K = KS_H[s], half = K/2;
        double ss = sig[s]*sig[s];
        double sn = 0.3989422804014327 / ss;
        double sg = 0.0, su = 0.0;
        for (int jj = 0; jj < WSTRIDE; ++jj){
            float g = 0.f, u = 0.f;
            if (jj < K){
                double t  = (double)(jj - half);
                double t2 = t*t;
                double e  = exp(-t2 / (2.0*ss));
                g = (float)(e * sn);
                u = (float)((t2 - ss) * e * sn);
                sg += (double)g; su += (double)u;
            }
            h_g2[s*WSTRIDE + jj] = hpackh(g, g);
            h_u2[s*WSTRIDE + jj] = hpackh(u, u);
            h_ugh[s*WSTRIDE + jj] = (uint)f2h_host(u) | ((uint)f2h_host(g) << 16);
            h_wg[s][jj] = g;
            h_wu[s][jj] = u;
        }
        h_cn[s] = -(float)(2.0 * sg * su / ((double)K * (double)K));

        for (int stream = 0; stream < 2; ++stream){
            for (int d = 0; d < DMAX; ++d){
                for (int lane = 0; lane < 32; ++lane){
                    int g_ = lane >> 2, j_ = lane & 3;
                    int b = 16*d + 2*j_;
                    uint a0 = (uint)wtap(s,stream, b     - g_    ) | ((uint)wtap(s,stream, b + 1 - g_    ) << 16);
                    uint a1 = (uint)wtap(s,stream, b     - g_ - 8) | ((uint)wtap(s,stream, b + 1 - g_ - 8) << 16);
                    uint a2 = (uint)wtap(s,stream, b + 8 - g_    ) | ((uint)wtap(s,stream, b + 9 - g_    ) << 16);
                    uint a3 = (uint)wtap(s,stream, b + 8 - g_ - 8) | ((uint)wtap(s,stream, b + 9 - g_ - 8) << 16);
                    size_t idx = ((((size_t)s*2 + stream)*DMAX + d)*32 + lane)*4;
                    h_afrag[idx+0] = a0; h_afrag[idx+1] = a1;
                    h_afrag[idx+2] = a2; h_afrag[idx+3] = a3;
                }
            }
        }
    }
}

// per-K smem sizes
static inline int hs_bytes(int K){
    int SH = ((K + 6)/4)*4;
    int TS = 508 + SH;
    int TSP = (TS + TS/8 + 3) & ~1;
    return TSP*16;
}
static inline int vs_sc_bytes(int K){
    int SV = ((K + 14)/8)*8;
    int TR = 120 + SV;
    return TR*128 + 64;
}
static inline int vs_mma_bytes(int K){
    int D = (K + 30)/16;
    int TR = 112 + 16*D;
    int TRu = TR/2 + 1;
    int XTB = 32*TRu*8;
    int SBB = TR*80 + 128*64;
    int MAXB = XTB > SBB ? XTB : SBB;
    return MAXB + 64;
}

// ---- capture-dependency helpers (CUDA 13 signatures; no allocations) ----
static bool is_capturing(){
    cudaStreamCaptureStatus st = cudaStreamCaptureStatusNone;
    cudaStreamIsCapturing((cudaStream_t)0, &st);
    return st == cudaStreamCaptureStatusActive;
}
static size_t get_deps(cudaGraphNode_t* out, size_t cap){
    cudaStreamCaptureStatus st;
    const cudaGraphNode_t* deps = nullptr;
    size_t n = 0;
    cudaStreamGetCaptureInfo((cudaStream_t)0, &st, nullptr, nullptr,
                             &deps, nullptr, &n);
    size_t m = (n < cap) ? n : cap;
    for (size_t i = 0; i < m; ++i) out[i] = deps[i];
    return m;
}
static void set_deps(cudaGraphNode_t* d, size_t n){
    cudaStreamUpdateCaptureDependencies((cudaStream_t)0, d, nullptr, n,
                                        cudaStreamSetCaptureDependencies);
}

extern "C" void kernel_launch(void* const* d_in, const int* in_sizes, int n_in,
                              void* d_out, int out_size)
{
    const float* input  = (const float*)d_in[0];
    const float* target = (const float*)d_in[1];
    float* out = (float*)d_out;

    build_weights();
    cudaMemcpyToSymbolAsync(c_g2,    h_g2,    sizeof(h_g2),    0, cudaMemcpyHostToDevice, 0);
    cudaMemcpyToSymbolAsync(c_u2,    h_u2,    sizeof(h_u2),    0, cudaMemcpyHostToDevice, 0);
    cudaMemcpyToSymbolAsync(c_ugh,   h_ugh,   sizeof(h_ugh),   0, cudaMemcpyHostToDevice, 0);
    cudaMemcpyToSymbolAsync(c_cn,    h_cn,    sizeof(h_cn),    0, cudaMemcpyHostToDevice, 0);
    cudaMemcpyToSymbolAsync(d_afrag, h_afrag, sizeof(h_afrag), 0, cudaMemcpyHostToDevice, 0);

    zero_acc<<<1, 64>>>();
    diff_prefix_kernel<<<dim3(512, NIMG), 256>>>(input, target);

    const bool cap = is_capturing();
    cudaGraphNode_t root[4];
    size_t nroot = 0;
    cudaGraphNode_t vjoin[6];
    size_t nj = 0;

    if (cap) nroot = get_deps(root, 4);

    const dim3 hgrid(128, NIMG);
    const dim3 vgrid(16, 4, NIMG);

    // large K -> tensor-core vpass
    hpass_k<155,5><<<hgrid, 128, hs_bytes(155)>>>();
    vpass_mma<155,5><<<vgrid, 256, vs_mma_bytes(155)>>>(10.f);
    if (cap){ nj += get_deps(vjoin + nj, 1); set_deps(root, nroot); }

    hpass_k<77,4><<<hgrid, 128, hs_bytes(77)>>>();
    vpass_mma<77,4><<<vgrid, 256, vs_mma_bytes(77)>>>(10.f);
    if (cap){ nj += get_deps(vjoin + nj, 1); set_deps(root, nroot); }

    // small K -> scalar HFMA2 vpass
    hpass_k<39,3><<<hgrid, 128, hs_bytes(39)>>>();
    vpass_sc<39,3><<<vgrid, 256, vs_sc_bytes(39)>>>(20.f);
    if (cap){ nj += get_deps(vjoin + nj, 1); set_deps(root, nroot); }

    hpass_k<21,2><<<hgrid, 128, hs_bytes(21)>>>();
    vpass_sc<21,2><<<vgrid, 256, vs_sc_bytes(21)>>>(400.f);
    if (cap){ nj += get_deps(vjoin + nj, 1); set_deps(root, nroot); }

    hpass_k<11,1><<<hgrid, 128, hs_bytes(11)>>>();
    vpass_sc<11,1><<<vgrid, 256, vs_sc_bytes(11)>>>(500.f);
    if (cap){ nj += get_deps(vjoin + nj, 1); set_deps(root, nroot); }

    hpass_k<5,0><<<hgrid, 128, hs_bytes(5)>>>();
    vpass_sc<5,0><<<vgrid, 256, vs_sc_bytes(5)>>>(600.f);
    if (cap){ nj += get_deps(vjoin + nj, 1); }

    if (cap && nj > 0) set_deps(vjoin, nj);
    final_kernel<<<1, 1>>>(out);
}